// round 9
// baseline (speedup 1.0000x reference)
#include <cuda_runtime.h>
#include <cstdint>

// ---------------- problem constants ----------------
#define Hc    128
#define H1c   129
#define FUSE  (H1c*H1c*H1c)     // 2,146,689
#define NROW  (H1c*H1c)         // 16641 (i,j) rows, each 129 kq long
#define Bq    64
#define N1    64
#define N2    32
#define NCTA  304
#define RPC   55                // (i,j)-rows per CTA (55*304 >= 16641)
#define NTHR  128               // 4 compute warps
#define KSTEPS 17               // ceil(129/8) k-steps of 8 per r (pad to 136)

// dynamic smem layout (floats)
#define SM_T      0             // T tile: 64 b x 137 (col0=1, 1..128=t, 129..135=0, pad) tf32
#define SM_PM     8768          // pm slice: RPC x 64                 (fp32)
#define SM_A2     12288         // 2 a_h columns x 64 b
#define SM_FLOATS 12416         // 49664 bytes

__device__ float g_partial[NCTA * Bq * N1];   // ~5 MB
__device__ float g_Y1[Bq * N1];

// ---------------- helpers ----------------
__device__ __forceinline__ uint32_t to_tf32(float f) {
    uint32_t u;
    asm("cvt.rna.tf32.f32 %0, %1;" : "=r"(u) : "f"(f));
    return u;
}
// D(16x8,f32) += A(16x8,tf32) * B(8x8,tf32)   row.col
__device__ __forceinline__ void mma_tf32(float* d, const uint32_t* a,
                                         uint32_t b0, uint32_t b1) {
    asm volatile(
        "mma.sync.aligned.m16n8k8.row.col.f32.tf32.tf32.f32 "
        "{%0,%1,%2,%3}, {%4,%5,%6,%7}, {%8,%9}, {%0,%1,%2,%3};"
        : "+f"(d[0]), "+f"(d[1]), "+f"(d[2]), "+f"(d[3])
        : "r"(a[0]), "r"(a[1]), "r"(a[2]), "r"(a[3]), "r"(b0), "r"(b1));
}

// ============================================================
// Kernel 1: factored GEMM.
//   For each (i,j)-row r:  G_r[64b x 64n] = T_h[64 x 129] @ W1_r[129 x 64]  (tf32 mma)
//   then D += pm[r,b] * G_r   (fp32 FFMA epilogue)
// A (T_h) is CTA-invariant in smem; B (W1) streamed by direct LDG with
// 1-step register prefetch. No per-tile syncs, no cp.async, no genF.
// ============================================================
__global__ void __launch_bounds__(NTHR, 2)
k_main(const float* __restrict__ v, const float* __restrict__ a,
       const float* __restrict__ t, const float* __restrict__ W1)
{
    extern __shared__ float sm[];
    float* sT  = sm + SM_T;      // [b*137 + c]
    float* sPM = sm + SM_PM;     // [rloc*64 + b]
    float* sA2 = sm + SM_A2;     // [sel*64 + b]
    float* vT  = sm + SM_T;      // staging alias: vT[j*65 + b] (<= 33280 B)

    const int tid  = threadIdx.x;
    const int wid  = tid >> 5;
    const int lane = tid & 31;
    const int cta  = blockIdx.x;

    const int r0    = cta * RPC;
    const int nrows = (r0 < NROW) ? min(RPC, NROW - r0) : 0;

    if (nrows <= 0) {            // idle CTA: zero partial, uniform exit
        float* out = &g_partial[cta * (Bq * N1)];
        for (int i = tid; i < Bq * N1; i += NTHR) out[i] = 0.f;
        return;
    }

    const int i0 = r0 / H1c;
    const int i1 = (r0 + nrows - 1) / H1c;   // i spans at most {i0, i1}

    // --- stage v transposed: vT[j][b] (coalesced read, conflict-free write) ---
    for (int idx = tid; idx < Bq * Hc; idx += NTHR) {
        int b = idx >> 7, c = idx & 127;
        vT[c * 65 + b] = v[idx];
    }
    // --- stage the (<=2) needed a_h columns ---
    {
        int c = tid >> 6, b = tid & 63;      // 128 threads -> 2 cols x 64 b
        int ii = c ? i1 : i0;
        sA2[c * 64 + b] = (ii == 0) ? 1.f : __ldg(&a[b * Hc + ii - 1]);
    }
    __syncthreads();

    // --- build pm slice: sPM[rloc][b] = a_h[b,i] * v_h[b,j]  (fp32) ---
    for (int idx = tid; idx < nrows * Bq; idx += NTHR) {
        int rloc = idx >> 6, b = idx & 63;
        int rg = r0 + rloc;
        int i  = rg / H1c;
        int j  = rg - i * H1c;
        float av = (i == i0) ? sA2[b] : sA2[64 + b];
        float vv = (j == 0) ? 1.f : vT[(j - 1) * 65 + b];
        sPM[idx] = av * vv;
    }
    __syncthreads();

    // --- build T tile (overwrites vT region): sT[b][c], tf32-rounded ---
    for (int idx = tid; idx < Bq * 137; idx += NTHR) {
        int b = idx / 137, c = idx - b * 137;
        float val = (c == 0) ? 1.f : ((c <= Hc) ? __ldg(&t[b * Hc + c - 1]) : 0.f);
        sT[idx] = __uint_as_float(to_tf32(val));
    }
    __syncthreads();

    // --- warp geometry: 4 warps, m32 x n32 tiles over D[64b x 64n] ---
    const int wm = wid & 1;
    const int wn = wid >> 1;
    const int g  = lane >> 2;
    const int tk = lane & 3;
    const int nb = wn * 32 + g;

    float dacc[2][4][4];
    #pragma unroll
    for (int mi = 0; mi < 2; mi++)
        #pragma unroll
        for (int nj = 0; nj < 4; nj++)
            #pragma unroll
            for (int q = 0; q < 4; q++) dacc[mi][nj][q] = 0.f;

    float bq[2][8];              // raw W1 prefetch regs (parity-indexed, unrolled)

    auto bload = [&](int r, int ks, float* dst) {
        long long kb = (long long)(r0 + r) * H1c + ks * 8;
        long long kA = kb + tk;
        long long kB = kb + 4 + tk;
        if (kA >= FUSE) kA = FUSE - 1;   // clamped rows multiply A-pad zeros
        if (kB >= FUSE) kB = FUSE - 1;
        const float* pA = W1 + kA * N1 + nb;
        const float* pB = W1 + kB * N1 + nb;
        #pragma unroll
        for (int nj = 0; nj < 4; nj++) {
            dst[nj * 2 + 0] = __ldg(pA + nj * 8);
            dst[nj * 2 + 1] = __ldg(pB + nj * 8);
        }
    };

    bload(0, 0, bq[0]);

    for (int r = 0; r < nrows; r++) {
        float gacc[2][4][4];
        #pragma unroll
        for (int mi = 0; mi < 2; mi++)
            #pragma unroll
            for (int nj = 0; nj < 4; nj++)
                #pragma unroll
                for (int q = 0; q < 4; q++) gacc[mi][nj][q] = 0.f;

        #pragma unroll
        for (int ks = 0; ks < KSTEPS; ks++) {
            const int cur = (r * KSTEPS + ks) & 1;   // compile-time after unroll
            // prefetch next step (crosses r boundary at ks==16)
            {
                int nr = r, nks = ks + 1;
                if (nks == KSTEPS) { nks = 0; nr = r + 1; }
                if (nr < nrows) bload(nr, nks, bq[cur ^ 1]);
            }
            // A fragments from resident sT (stride 137: conflict-free)
            uint32_t afr[2][4];
            const int c = ks * 8 + tk;
            #pragma unroll
            for (int mi = 0; mi < 2; mi++) {
                const int rr = wm * 32 + mi * 16 + g;
                afr[mi][0] = __float_as_uint(sT[rr * 137 + c]);
                afr[mi][1] = __float_as_uint(sT[(rr + 8) * 137 + c]);
                afr[mi][2] = __float_as_uint(sT[rr * 137 + c + 4]);
                afr[mi][3] = __float_as_uint(sT[(rr + 8) * 137 + c + 4]);
            }
            #pragma unroll
            for (int nj = 0; nj < 4; nj++) {
                uint32_t b0 = to_tf32(bq[cur][nj * 2 + 0]);
                uint32_t b1 = to_tf32(bq[cur][nj * 2 + 1]);
                mma_tf32(gacc[0][nj], afr[0], b0, b1);
                mma_tf32(gacc[1][nj], afr[1], b0, b1);
            }
        }

        // epilogue: D += pm[r,b] * G_r   (pm in full fp32)
        #pragma unroll
        for (int mi = 0; mi < 2; mi++) {
            const int rrow = wm * 32 + mi * 16 + g;
            float p0 = sPM[r * 64 + rrow];
            float p1 = sPM[r * 64 + rrow + 8];
            #pragma unroll
            for (int nj = 0; nj < 4; nj++) {
                dacc[mi][nj][0] += p0 * gacc[mi][nj][0];
                dacc[mi][nj][1] += p0 * gacc[mi][nj][1];
                dacc[mi][nj][2] += p1 * gacc[mi][nj][2];
                dacc[mi][nj][3] += p1 * gacc[mi][nj][3];
            }
        }
    }

    // --- write partial tile: rows g,g+8; cols 2tk,2tk+1 ---
    float* base = &g_partial[cta * (Bq * N1)];
    #pragma unroll
    for (int mi = 0; mi < 2; mi++) {
        const int rr = wm * 32 + mi * 16 + g;
        #pragma unroll
        for (int nj = 0; nj < 4; nj++) {
            const int n = wn * 32 + nj * 8 + 2 * tk;
            *reinterpret_cast<float2*>(base + rr * N1 + n) =
                make_float2(dacc[mi][nj][0], dacc[mi][nj][1]);
            *reinterpret_cast<float2*>(base + (rr + 8) * N1 + n) =
                make_float2(dacc[mi][nj][2], dacc[mi][nj][3]);
        }
    }
}

// ============================================================
// Kernel 2: reduce partials, +b1, relu -> g_Y1
// ============================================================
__global__ void k_reduce(const float* __restrict__ b1)
{
    int tix = blockIdx.x * blockDim.x + threadIdx.x;   // 0..4095
    float s = 0.f;
    #pragma unroll 4
    for (int c = 0; c < NCTA; c++)
        s += g_partial[c * (Bq * N1) + tix];
    s += b1[tix & (N1 - 1)];
    g_Y1[tix] = fmaxf(s, 0.f);
}

// ============================================================
// Kernel 3: tail MLP — 256 threads stage everything to smem first
// (R8's 64-thread version was DRAM-latency-chain bound at 13.9us)
// ============================================================
__global__ void k_tail(const float* __restrict__ W2, const float* __restrict__ b2,
                       const float* __restrict__ W3, const float* __restrict__ b3,
                       float* __restrict__ out)
{
    __shared__ float sW2[N1 * N2];
    __shared__ float sY1[Bq * N1];
    __shared__ float sW3[N2];
    __shared__ float sB2[N2];
    int tid = threadIdx.x;
    for (int i = tid; i < N1 * N2; i += 256) sW2[i] = W2[i];
    for (int i = tid; i < Bq * N1; i += 256) sY1[i] = g_Y1[i];
    if (tid < N2) { sW3[tid] = W3[tid]; sB2[tid] = b2[tid]; }
    __syncthreads();

    if (tid < Bq) {
        float r = b3[0];
        #pragma unroll 4
        for (int j = 0; j < N2; j++) {
            float s = sB2[j];
            #pragma unroll
            for (int o = 0; o < N1; o++) s += sY1[tid * N1 + o] * sW2[o * N2 + j];
            r += fmaxf(s, 0.f) * sW3[j];
        }
        out[tid] = r;
    }
}

// ============================================================
// Launch: v, a, t, W1, b1, W2, b2, W3, b3 ; out float[64]
// ============================================================
extern "C" void kernel_launch(void* const* d_in, const int* in_sizes, int n_in,
                              void* d_out, int out_size)
{
    const float *v  = (const float*)d_in[0];
    const float *a  = (const float*)d_in[1];
    const float *t  = (const float*)d_in[2];
    const float *W1 = (const float*)d_in[3];
    const float *b1 = (const float*)d_in[4];
    const float *W2 = (const float*)d_in[5];
    const float *b2 = (const float*)d_in[6];
    const float *W3 = (const float*)d_in[7];
    const float *b3 = (const float*)d_in[8];
    float *out = (float*)d_out;

    cudaFuncSetAttribute(k_main, cudaFuncAttributeMaxDynamicSharedMemorySize,
                         SM_FLOATS * 4);

    k_main<<<NCTA, NTHR, SM_FLOATS * 4>>>(v, a, t, W1);
    k_reduce<<<(Bq * N1) / 256, 256>>>(b1);
    k_tail<<<1, 256>>>(W2, b2, W3, b3, out);
}

// round 10
// speedup vs baseline: 2.7298x; 2.7298x over previous
#include <cuda_runtime.h>
#include <cstdint>

// ---------------- problem constants ----------------
#define Hc    128
#define H1c   129
#define FUSE  (H1c*H1c*H1c)     // 2,146,689
#define NROW  (H1c*H1c)         // 16641
#define Bq    64
#define N1    64
#define N2    32
#define TK    32                // k per tile (4 mma k-steps of 8)
#define NCTA  304
#define NTHR  256
#define RPC   55                // (i,j)-rows per CTA (55*304 >= 16641)

#define SA_STRIDE 36            // floats per A row  (conflict-free frag loads)
#define SB_STRIDE 72            // floats per B k-row (conflict-free frag loads)

// dynamic smem layout (floats)
#define SM_A      0                         // sA: 2 x 64 x 36  = 4608
#define SM_B      4608                      // sB: 2 x 32 x 72  = 4608
#define SM_STAGE  9216                      // stage: 2 x 2048  = 4096 (16B-aligned)
#define SM_MBAR   13312                     // 2 mbarriers (4 floats)
#define SM_FLOATS 13316                     // 53264 bytes

__device__ float g_partial[NCTA * Bq * N1];   // ~5 MB
__device__ float g_Y1[Bq * N1];
__device__ float g_pm[NROW * Bq];             // pm[r][b] = a_h[b,i]*v_h[b,j]
__device__ float g_tT2[Bq * H1c];             // tT2[b][kq] = t_h[b,kq]

// ---------------- helpers ----------------
__device__ __forceinline__ uint32_t smem_u32(const void* p) {
    uint32_t a;
    asm("{ .reg .u64 t; cvta.to.shared.u64 t, %1; cvt.u32.u64 %0, t; }" : "=r"(a) : "l"(p));
    return a;
}
__device__ __forceinline__ uint32_t to_tf32(float f) {
    uint32_t u;
    asm("cvt.rna.tf32.f32 %0, %1;" : "=r"(u) : "f"(f));
    return u;
}
__device__ __forceinline__ void mbar_init(uint32_t a, uint32_t cnt) {
    asm volatile("mbarrier.init.shared.b64 [%0], %1;" :: "r"(a), "r"(cnt) : "memory");
}
__device__ __forceinline__ void mbar_expect_tx(uint32_t a, uint32_t bytes) {
    asm volatile("mbarrier.arrive.expect_tx.shared.b64 _, [%0], %1;"
                 :: "r"(a), "r"(bytes) : "memory");
}
__device__ __forceinline__ void bulk_g2s(uint32_t dst, const void* src,
                                         uint32_t bytes, uint32_t mbar) {
    asm volatile(
        "cp.async.bulk.shared::cluster.global.mbarrier::complete_tx::bytes "
        "[%0], [%1], %2, [%3];"
        :: "r"(dst), "l"(src), "r"(bytes), "r"(mbar) : "memory");
}
__device__ __forceinline__ void mbar_wait(uint32_t a, uint32_t par) {
    uint32_t done;
    asm volatile("{\n\t.reg .pred p;\n\t"
                 "mbarrier.try_wait.parity.acquire.cta.shared::cta.b64 p, [%1], %2;\n\t"
                 "selp.b32 %0,1,0,p;\n\t}" : "=r"(done) : "r"(a), "r"(par) : "memory");
    if (!done) {
        asm volatile("{\n\t.reg .pred P1;\n\tW%=:\n\t"
                     "mbarrier.try_wait.parity.acquire.cta.shared::cta.b64 P1, [%0], %1, 0x989680;\n\t"
                     "@P1 bra.uni D%=;\n\tbra.uni W%=;\n\tD%=:\n\t}"
                     :: "r"(a), "r"(par) : "memory");
    }
}
// D(16x8,f32) += A(16x8,tf32) * B(8x8,tf32)   row.col
__device__ __forceinline__ void mma_tf32(float* d, const uint32_t* a,
                                         uint32_t b0, uint32_t b1) {
    asm volatile(
        "mma.sync.aligned.m16n8k8.row.col.f32.tf32.tf32.f32 "
        "{%0,%1,%2,%3}, {%4,%5,%6,%7}, {%8,%9}, {%0,%1,%2,%3};"
        : "+f"(d[0]), "+f"(d[1]), "+f"(d[2]), "+f"(d[3])
        : "r"(a[0]), "r"(a[1]), "r"(a[2]), "r"(a[3]), "r"(b0), "r"(b1));
}

// ============================================================
// Kernel 0: prep
// ============================================================
__global__ void k_prep(const float* __restrict__ v, const float* __restrict__ a,
                       const float* __restrict__ t)
{
    int idx = blockIdx.x * blockDim.x + threadIdx.x;
    if (idx < NROW * Bq) {
        int b = idx & (Bq - 1);
        int r = idx >> 6;
        int i = r / H1c;
        int j = r - i * H1c;
        float av = (i == 0) ? 1.f : __ldg(&a[b * Hc + (i - 1)]);
        float vv = (j == 0) ? 1.f : __ldg(&v[b * Hc + (j - 1)]);
        g_pm[idx] = av * vv;
    } else if (idx < NROW * Bq + Bq * H1c) {
        int j  = idx - NROW * Bq;
        int b  = j / H1c;
        int kq = j - b * H1c;
        g_tT2[j] = (kq == 0) ? 1.f : __ldg(&t[b * Hc + (kq - 1)]);
    }
}

// ============================================================
// Kernel 1: tf32 mma.sync partial GEMM, W1 fed by cp.async.bulk.
//   stage[buf] <- 8KB W1 tile (1 bulk copy, mbarrier complete_tx)
//   repack stage -> sB[buf] (stride 72, tf32-rounded)
//   genF -> sA[buf] (stride 36, tf32-rounded)
//   1 __syncthreads per tile; MMA warps lag one buffer behind.
// ============================================================
__global__ void __launch_bounds__(NTHR, 2)
k_main(const float* __restrict__ W1)
{
    extern __shared__ float sm[];
    float* sA = sm + SM_A;                    // [buf*2304 + b*36 + k]
    float* sB = sm + SM_B;                    // [buf*2304 + k*72 + n]
    float* sS = sm + SM_STAGE;                // [buf*2048 + k*64 + n]
    const uint32_t base = smem_u32(sm);
    const uint32_t stg_u = base + SM_STAGE * 4;
    const uint32_t mb[2] = { base + SM_MBAR * 4, base + SM_MBAR * 4 + 8 };

    const int tid  = threadIdx.x;
    const int wid  = tid >> 5;
    const int lane = tid & 31;
    const int cta  = blockIdx.x;

    const int r0     = cta * RPC;
    const int nrows  = (r0 < NROW) ? min(RPC, NROW - r0) : 0;
    const int nk     = nrows * H1c;
    const int ntiles = (nk + TK - 1) / TK;
    const long long k0 = (long long)r0 * H1c;

    if (ntiles == 0) {            // idle CTA: zero partial, uniform exit
        float* out = &g_partial[cta * (Bq * N1)];
        for (int i = tid; i < Bq * N1; i += NTHR) out[i] = 0.f;
        return;
    }

    if (tid == 0) { mbar_init(mb[0], 1); mbar_init(mb[1], 1); }
    __syncthreads();

    // --- producer: one bulk copy per tile (clamped at FUSE for the last tile) ---
    auto issue = [&](int tl) {
        if (tl < ntiles && tid == 0) {
            const int buf = tl & 1;
            const long long kb = k0 + (long long)tl * TK;
            long long rem = ((long long)FUSE - kb) * (N1 * 4);
            uint32_t bytes = (rem < TK * N1 * 4) ? (uint32_t)rem : (uint32_t)(TK * N1 * 4);
            mbar_expect_tx(mb[buf], bytes);
            bulk_g2s(stg_u + buf * (TK * N1 * 4), W1 + kb * N1, bytes, mb[buf]);
        }
    };

    // --- F tile -> sA[buf]; lanes walk k (conflict-free STS, coalesced LDG) ---
    auto genF = [&](int tl, int buf) {
        const int kbl = tl * TK;
        #pragma unroll
        for (int p = 0; p < 8; p++) {
            int b  = p * 8 + wid;
            int kl = kbl + lane;
            float f = 0.f;
            if (kl < nk) {
                int row = kl / H1c;
                int kq  = kl - row * H1c;
                f = __ldg(&g_pm[(r0 + row) * Bq + b]) * __ldg(&g_tT2[b * H1c + kq]);
            }
            sA[buf * (Bq * SA_STRIDE) + b * SA_STRIDE + lane] = __uint_as_float(to_tf32(f));
        }
    };

    // --- repack stage[buf] -> sB[buf] (stride 72), tf32-rounded ---
    auto repack = [&](int buf) {
        const float* st = sS + buf * (TK * N1);
        float* dst = sB + buf * (TK * SB_STRIDE);
        #pragma unroll
        for (int p = 0; p < 2; p++) {
            int idx = p * NTHR + tid;          // 0..511
            int kk = idx >> 4, seg = idx & 15;
            float4 w = *reinterpret_cast<const float4*>(st + kk * N1 + seg * 4);
            uint4 u = make_uint4(to_tf32(w.x), to_tf32(w.y), to_tf32(w.z), to_tf32(w.w));
            *reinterpret_cast<uint4*>(dst + kk * SB_STRIDE + seg * 4) = u;
        }
    };

    // compute-warp geometry (warps 0..3, m32n32 each)
    const int wm = wid & 1;
    const int wn = (wid >> 1) & 1;
    const int g  = lane >> 2;
    const int tk = lane & 3;

    float acc[2][4][4];
    #pragma unroll
    for (int mi = 0; mi < 2; mi++)
        #pragma unroll
        for (int nj = 0; nj < 4; nj++)
            #pragma unroll
            for (int q = 0; q < 4; q++) acc[mi][nj][q] = 0.f;

    issue(0); issue(1);

    int ph[2] = {0, 0};
    for (int tl = 0; tl < ntiles; tl++) {
        const int buf = tl & 1;
        mbar_wait(mb[buf], ph[buf]); ph[buf] ^= 1;   // stage[buf] full
        repack(buf);
        genF(tl, buf);
        __syncthreads();           // sA/sB[buf] ready; stage[buf] fully consumed
        issue(tl + 2);             // refill this stage slot

        if (wid < 4) {
            const float* A = sA + buf * (Bq * SA_STRIDE);
            const float* B = sB + buf * (TK * SB_STRIDE);
            #pragma unroll
            for (int ks = 0; ks < 4; ks++) {
                uint32_t a[2][4];
                const int c = ks * 8 + tk;
                #pragma unroll
                for (int mi = 0; mi < 2; mi++) {
                    const int r = wm * 32 + mi * 16 + g;
                    a[mi][0] = __float_as_uint(A[r       * SA_STRIDE + c]);
                    a[mi][1] = __float_as_uint(A[(r + 8) * SA_STRIDE + c]);
                    a[mi][2] = __float_as_uint(A[r       * SA_STRIDE + c + 4]);
                    a[mi][3] = __float_as_uint(A[(r + 8) * SA_STRIDE + c + 4]);
                }
                #pragma unroll
                for (int nj = 0; nj < 4; nj++) {
                    const int n = wn * 32 + nj * 8 + g;
                    uint32_t b0 = __float_as_uint(B[(ks * 8 + tk)     * SB_STRIDE + n]);
                    uint32_t b1 = __float_as_uint(B[(ks * 8 + 4 + tk) * SB_STRIDE + n]);
                    mma_tf32(acc[0][nj], a[0], b0, b1);
                    mma_tf32(acc[1][nj], a[1], b0, b1);
                }
            }
        }
        // no second barrier: MMA(tl) reads buf; the next write to buf
        // (repack/genF at tl+2) happens only after __syncthreads(tl+1),
        // which MMA warps reach only after finishing MMA(tl).
    }

    // --- write partial tile: rows g,g+8; cols 2tk,2tk+1 ---
    if (wid < 4) {
        float* basep = &g_partial[cta * (Bq * N1)];
        #pragma unroll
        for (int mi = 0; mi < 2; mi++) {
            const int r = wm * 32 + mi * 16 + g;
            #pragma unroll
            for (int nj = 0; nj < 4; nj++) {
                const int n = wn * 32 + nj * 8 + 2 * tk;
                *reinterpret_cast<float2*>(basep + r * N1 + n) =
                    make_float2(acc[mi][nj][0], acc[mi][nj][1]);
                *reinterpret_cast<float2*>(basep + (r + 8) * N1 + n) =
                    make_float2(acc[mi][nj][2], acc[mi][nj][3]);
            }
        }
    }
}

// ============================================================
// Kernel 2: reduce partials, +b1, relu -> g_Y1
// ============================================================
__global__ void k_reduce(const float* __restrict__ b1)
{
    int tix = blockIdx.x * blockDim.x + threadIdx.x;   // 0..4095
    float s = 0.f;
    #pragma unroll 4
    for (int c = 0; c < NCTA; c++)
        s += g_partial[c * (Bq * N1) + tix];
    s += b1[tix & (N1 - 1)];
    g_Y1[tix] = fmaxf(s, 0.f);
}

// ============================================================
// Kernel 3: tail MLP (256-thread smem-staged)
// ============================================================
__global__ void k_tail(const float* __restrict__ W2, const float* __restrict__ b2,
                       const float* __restrict__ W3, const float* __restrict__ b3,
                       float* __restrict__ out)
{
    __shared__ float sW2[N1 * N2];
    __shared__ float sY1[Bq * N1];
    __shared__ float sW3[N2];
    __shared__ float sB2[N2];
    int tid = threadIdx.x;
    for (int i = tid; i < N1 * N2; i += 256) sW2[i] = W2[i];
    for (int i = tid; i < Bq * N1; i += 256) sY1[i] = g_Y1[i];
    if (tid < N2) { sW3[tid] = W3[tid]; sB2[tid] = b2[tid]; }
    __syncthreads();

    if (tid < Bq) {
        float r = b3[0];
        #pragma unroll 4
        for (int j = 0; j < N2; j++) {
            float s = sB2[j];
            #pragma unroll
            for (int o = 0; o < N1; o++) s += sY1[tid * N1 + o] * sW2[o * N2 + j];
            r += fmaxf(s, 0.f) * sW3[j];
        }
        out[tid] = r;
    }
}

// ============================================================
// Launch: v, a, t, W1, b1, W2, b2, W3, b3 ; out float[64]
// ============================================================
extern "C" void kernel_launch(void* const* d_in, const int* in_sizes, int n_in,
                              void* d_out, int out_size)
{
    const float *v  = (const float*)d_in[0];
    const float *a  = (const float*)d_in[1];
    const float *t  = (const float*)d_in[2];
    const float *W1 = (const float*)d_in[3];
    const float *b1 = (const float*)d_in[4];
    const float *W2 = (const float*)d_in[5];
    const float *b2 = (const float*)d_in[6];
    const float *W3 = (const float*)d_in[7];
    const float *b3 = (const float*)d_in[8];
    float *out = (float*)d_out;

    cudaFuncSetAttribute(k_main, cudaFuncAttributeMaxDynamicSharedMemorySize,
                         SM_FLOATS * 4);

    const int prep_elems = NROW * Bq + Bq * H1c;
    k_prep<<<(prep_elems + NTHR - 1) / NTHR, NTHR>>>(v, a, t);
    k_main<<<NCTA, NTHR, SM_FLOATS * 4>>>(W1);
    k_reduce<<<(Bq * N1) / 256, 256>>>(b1);
    k_tail<<<1, 256>>>(W2, b2, W3, b3, out);
}

// round 11
// speedup vs baseline: 3.5368x; 1.2956x over previous
#include <cuda_runtime.h>
#include <cstdint>

// ---------------- problem constants ----------------
#define Hc    128
#define H1c   129
#define FUSE  (H1c*H1c*H1c)     // 2,146,689 = 16641 * 129 exactly
#define NROW  (H1c*H1c)         // 16641 (i,j) rows, each 129 k long
#define Bq    64
#define N1    64
#define N2    32
#define NCTA  152               // 1 CTA per SM
#define NTHR  512               // 16 warps
#define RPC   110               // (i,j)-rows per CTA (152*110 = 16720 >= 16641)

// smem layout (floats)
#define ST_STRIDE 140           // sT row stride (conflict-free frag LDS banks)
#define SB_STRIDE 72            // sB k-row stride (conflict-free B frag LDS)
#define SM_T      0                             // sT: 64 x 140          = 8960
#define SM_STAGE  8960                          // stage: 2 x 129*64     = 16512
#define SM_SB     25472                         // sB: 2 x 129*72        = 18576
#define SM_MBAR   44048                         // 2 mbarriers
#define SM_FLOATS 44052                         // 176208 bytes

#define R_BYTES   (H1c * N1 * 4)                // 33024 B per r slab

__device__ float g_partial[NCTA * Bq * N1];
__device__ float g_Y1[Bq * N1];
__device__ float g_pm[NROW * Bq];               // pm[r][b] = a_h[b,i]*v_h[b,j]

// ---------------- helpers ----------------
__device__ __forceinline__ uint32_t smem_u32(const void* p) {
    uint32_t a;
    asm("{ .reg .u64 t; cvta.to.shared.u64 t, %1; cvt.u32.u64 %0, t; }" : "=r"(a) : "l"(p));
    return a;
}
__device__ __forceinline__ uint32_t to_tf32(float f) {
    uint32_t u;
    asm("cvt.rna.tf32.f32 %0, %1;" : "=r"(u) : "f"(f));
    return u;
}
__device__ __forceinline__ void mbar_init(uint32_t a, uint32_t cnt) {
    asm volatile("mbarrier.init.shared.b64 [%0], %1;" :: "r"(a), "r"(cnt) : "memory");
}
__device__ __forceinline__ void mbar_expect_tx(uint32_t a, uint32_t bytes) {
    asm volatile("mbarrier.arrive.expect_tx.shared.b64 _, [%0], %1;"
                 :: "r"(a), "r"(bytes) : "memory");
}
__device__ __forceinline__ void bulk_g2s(uint32_t dst, const void* src,
                                         uint32_t bytes, uint32_t mbar) {
    asm volatile(
        "cp.async.bulk.shared::cluster.global.mbarrier::complete_tx::bytes "
        "[%0], [%1], %2, [%3];"
        :: "r"(dst), "l"(src), "r"(bytes), "r"(mbar) : "memory");
}
__device__ __forceinline__ void mbar_wait(uint32_t a, uint32_t par) {
    uint32_t done;
    asm volatile("{\n\t.reg .pred p;\n\t"
                 "mbarrier.try_wait.parity.acquire.cta.shared::cta.b64 p, [%1], %2;\n\t"
                 "selp.b32 %0,1,0,p;\n\t}" : "=r"(done) : "r"(a), "r"(par) : "memory");
    if (!done) {
        asm volatile("{\n\t.reg .pred P1;\n\tW%=:\n\t"
                     "mbarrier.try_wait.parity.acquire.cta.shared::cta.b64 P1, [%0], %1, 0x989680;\n\t"
                     "@P1 bra.uni D%=;\n\tbra.uni W%=;\n\tD%=:\n\t}"
                     :: "r"(a), "r"(par) : "memory");
    }
}
// D(16x8,f32) += A(16x8,tf32) * B(8x8,tf32)   row.col
__device__ __forceinline__ void mma_tf32(float* d, const uint32_t* a,
                                         uint32_t b0, uint32_t b1) {
    asm volatile(
        "mma.sync.aligned.m16n8k8.row.col.f32.tf32.tf32.f32 "
        "{%0,%1,%2,%3}, {%4,%5,%6,%7}, {%8,%9}, {%0,%1,%2,%3};"
        : "+f"(d[0]), "+f"(d[1]), "+f"(d[2]), "+f"(d[3])
        : "r"(a[0]), "r"(a[1]), "r"(a[2]), "r"(a[3]), "r"(b0), "r"(b1));
}

// ============================================================
// Kernel 0: prep — g_pm[r*64+b] = a_h[b, r/129] * v_h[b, r%129]
// ============================================================
__global__ void k_prep(const float* __restrict__ v, const float* __restrict__ a)
{
    int idx = blockIdx.x * blockDim.x + threadIdx.x;
    if (idx < NROW * Bq) {
        int b = idx & (Bq - 1);
        int r = idx >> 6;
        int i = r / H1c;
        int j = r - i * H1c;
        float av = (i == 0) ? 1.f : __ldg(&a[b * Hc + (i - 1)]);
        float vv = (j == 0) ? 1.f : __ldg(&v[b * Hc + (j - 1)]);
        g_pm[idx] = av * vv;
    }
}

// ============================================================
// Kernel 1: factored GEMM, per-r granularity.
//   per r:  G = T_h[64 x 129] @ W1_r[129 x 64]  (16 ks tf32 MMA + fp32 rank-1)
//           D += pm[r,:] (x) G                  (fp32 epilogue)
// A (T_h) frags live in REGISTERS (loop-invariant). W1_r arrives as one
// 33KB cp.async.bulk into stage[buf], repacked (stride 72, cvt.rna) to sB[buf].
// One __syncthreads per r. Double-buffered; bulk(r+1) overlaps MMA(r).
// ============================================================
__global__ void __launch_bounds__(NTHR, 1)
k_main(const float* __restrict__ t, const float* __restrict__ W1)
{
    extern __shared__ float sm[];
    float* sT = sm + SM_T;                       // [b*140 + c], c=0..128
    float* sS = sm + SM_STAGE;                   // [buf*8256 + k*64 + n]
    float* sB = sm + SM_SB;                      // [buf*9288 + k*72 + n]
    const uint32_t base = smem_u32(sm);
    const uint32_t stg_u = base + SM_STAGE * 4;
    const uint32_t mb[2] = { base + SM_MBAR * 4, base + SM_MBAR * 4 + 8 };

    const int tid  = threadIdx.x;
    const int wid  = tid >> 5;
    const int lane = tid & 31;
    const int cta  = blockIdx.x;

    const int r0    = cta * RPC;
    const int nrows = (r0 < NROW) ? min(RPC, NROW - r0) : 0;

    if (nrows <= 0) {
        float* out = &g_partial[cta * (Bq * N1)];
        for (int i = tid; i < Bq * N1; i += NTHR) out[i] = 0.f;
        return;
    }

    // --- build sT: T_h[b][c], c 0..128; tf32-rounded for MMA cols (c<128),
    //     raw fp32 at c==128 (used by the fp32 rank-1 step) ---
    for (int idx = tid; idx < Bq * H1c; idx += NTHR) {
        int b = idx / H1c;
        int c = idx - b * H1c;
        float val = (c == 0) ? 1.f : __ldg(&t[b * Hc + c - 1]);
        sT[b * ST_STRIDE + c] = (c < 128) ? __uint_as_float(to_tf32(val)) : val;
    }
    if (tid == 0) {
        mbar_init(mb[0], 1); mbar_init(mb[1], 1);
        mbar_expect_tx(mb[0], R_BYTES);
    }
    __syncthreads();
    if (tid == 0)
        bulk_g2s(stg_u, W1 + (long long)r0 * H1c * N1, R_BYTES, mb[0]);

    // --- warp geometry: 16 warps = 4 m16 x 4 n16 tiles over D[64b x 64n] ---
    const int wm = wid & 3;           // m16 tile index
    const int wn = wid >> 2;          // n16 tile index
    const int g  = lane >> 2;
    const int tk = lane & 3;
    const int rowA  = (wm * 16 + g) * ST_STRIDE;
    const int rowA8 = rowA + 8 * ST_STRIDE;

    // --- preload loop-invariant A fragments (T_h) into registers ---
    uint32_t afr[16][4];
    #pragma unroll
    for (int ks = 0; ks < 16; ks++) {
        const int c = ks * 8 + tk;
        afr[ks][0] = __float_as_uint(sT[rowA  + c]);
        afr[ks][1] = __float_as_uint(sT[rowA8 + c]);
        afr[ks][2] = __float_as_uint(sT[rowA  + c + 4]);
        afr[ks][3] = __float_as_uint(sT[rowA8 + c + 4]);
    }
    const float ar0 = sT[rowA  + 128];   // raw fp32 T_h[.,128]
    const float ar1 = sT[rowA8 + 128];

    float dacc[2][4];
    #pragma unroll
    for (int nj = 0; nj < 2; nj++)
        #pragma unroll
        for (int q = 0; q < 4; q++) dacc[nj][q] = 0.f;

    int ph[2] = {0, 0};
    for (int r = 0; r < nrows; r++) {
        const int buf = r & 1;
        mbar_wait(mb[buf], ph[buf]); ph[buf] ^= 1;     // stage[buf] full

        // repack stage[buf] -> sB[buf] (stride 72, tf32-rounded), all 129 rows
        {
            const float* st = sS + buf * (H1c * N1);
            float* dst = sB + buf * (H1c * SB_STRIDE);
            #pragma unroll
            for (int p = 0; p < 5; p++) {
                int idx = p * NTHR + tid;              // 0..2063 (129*16)
                if (idx < H1c * 16) {
                    int kk = idx >> 4, seg = idx & 15;
                    float4 w = *reinterpret_cast<const float4*>(st + kk * N1 + seg * 4);
                    uint4 u = make_uint4(to_tf32(w.x), to_tf32(w.y),
                                         to_tf32(w.z), to_tf32(w.w));
                    *reinterpret_cast<uint4*>(dst + kk * SB_STRIDE + seg * 4) = u;
                }
            }
        }
        if (tid == 0 && r + 1 < nrows)
            mbar_expect_tx(mb[buf ^ 1], R_BYTES);       // expect BEFORE copy issues
        __syncthreads();   // repack visible; all warps done MMA[r-1] (stage[buf^1] free)
        if (tid == 0 && r + 1 < nrows)
            bulk_g2s(stg_u + (buf ^ 1) * (H1c * N1 * 4),
                     W1 + (long long)(r0 + r + 1) * H1c * N1, R_BYTES, mb[buf ^ 1]);

        // --- G = T_h @ W1_r : 16 tf32 k-steps ---
        const float* Bb = sB + buf * (H1c * SB_STRIDE);
        float gacc[2][4];
        #pragma unroll
        for (int nj = 0; nj < 2; nj++)
            #pragma unroll
            for (int q = 0; q < 4; q++) gacc[nj][q] = 0.f;

        #pragma unroll
        for (int ks = 0; ks < 16; ks++) {
            #pragma unroll
            for (int nj = 0; nj < 2; nj++) {
                const int n = wn * 16 + nj * 8 + g;
                uint32_t b0 = __float_as_uint(Bb[(ks * 8 + tk)     * SB_STRIDE + n]);
                uint32_t b1 = __float_as_uint(Bb[(ks * 8 + 4 + tk) * SB_STRIDE + n]);
                mma_tf32(gacc[nj], afr[ks], b0, b1);
            }
        }
        // fp32 rank-1 for k = 128 (the 129th column of this r)
        #pragma unroll
        for (int nj = 0; nj < 2; nj++) {
            float2 ww = *reinterpret_cast<const float2*>(
                Bb + 128 * SB_STRIDE + wn * 16 + nj * 8 + 2 * tk);
            gacc[nj][0] += ar0 * ww.x;  gacc[nj][1] += ar0 * ww.y;
            gacc[nj][2] += ar1 * ww.x;  gacc[nj][3] += ar1 * ww.y;
        }
        // epilogue: D += pm[r,row] * G   (pm full fp32)
        {
            const float* pmr = &g_pm[(long long)(r0 + r) * Bq];
            float p0 = __ldg(pmr + wm * 16 + g);
            float p1 = __ldg(pmr + wm * 16 + g + 8);
            #pragma unroll
            for (int nj = 0; nj < 2; nj++) {
                dacc[nj][0] += p0 * gacc[nj][0];
                dacc[nj][1] += p0 * gacc[nj][1];
                dacc[nj][2] += p1 * gacc[nj][2];
                dacc[nj][3] += p1 * gacc[nj][3];
            }
        }
    }

    // --- write partial tile: rows g,g+8; cols 2tk,2tk+1 within m16n16 tile ---
    float* basep = &g_partial[cta * (Bq * N1)];
    #pragma unroll
    for (int nj = 0; nj < 2; nj++) {
        const int rr = wm * 16 + g;
        const int n  = wn * 16 + nj * 8 + 2 * tk;
        *reinterpret_cast<float2*>(basep + rr * N1 + n) =
            make_float2(dacc[nj][0], dacc[nj][1]);
        *reinterpret_cast<float2*>(basep + (rr + 8) * N1 + n) =
            make_float2(dacc[nj][2], dacc[nj][3]);
    }
}

// ============================================================
// Kernel 2: reduce partials, +b1, relu -> g_Y1
// ============================================================
__global__ void k_reduce(const float* __restrict__ b1)
{
    int tix = blockIdx.x * blockDim.x + threadIdx.x;   // 0..4095
    float s = 0.f;
    #pragma unroll 4
    for (int c = 0; c < NCTA; c++)
        s += g_partial[c * (Bq * N1) + tix];
    s += b1[tix & (N1 - 1)];
    g_Y1[tix] = fmaxf(s, 0.f);
}

// ============================================================
// Kernel 3: tail MLP (256-thread smem-staged)
// ============================================================
__global__ void k_tail(const float* __restrict__ W2, const float* __restrict__ b2,
                       const float* __restrict__ W3, const float* __restrict__ b3,
                       float* __restrict__ out)
{
    __shared__ float sW2[N1 * N2];
    __shared__ float sY1[Bq * N1];
    __shared__ float sW3[N2];
    __shared__ float sB2[N2];
    int tid = threadIdx.x;
    for (int i = tid; i < N1 * N2; i += 256) sW2[i] = W2[i];
    for (int i = tid; i < Bq * N1; i += 256) sY1[i] = g_Y1[i];
    if (tid < N2) { sW3[tid] = W3[tid]; sB2[tid] = b2[tid]; }
    __syncthreads();

    if (tid < Bq) {
        float r = b3[0];
        #pragma unroll 4
        for (int j = 0; j < N2; j++) {
            float s = sB2[j];
            #pragma unroll
            for (int o = 0; o < N1; o++) s += sY1[tid * N1 + o] * sW2[o * N2 + j];
            r += fmaxf(s, 0.f) * sW3[j];
        }
        out[tid] = r;
    }
}

// ============================================================
// Launch: v, a, t, W1, b1, W2, b2, W3, b3 ; out float[64]
// ============================================================
extern "C" void kernel_launch(void* const* d_in, const int* in_sizes, int n_in,
                              void* d_out, int out_size)
{
    const float *v  = (const float*)d_in[0];
    const float *a  = (const float*)d_in[1];
    const float *t  = (const float*)d_in[2];
    const float *W1 = (const float*)d_in[3];
    const float *b1 = (const float*)d_in[4];
    const float *W2 = (const float*)d_in[5];
    const float *b2 = (const float*)d_in[6];
    const float *W3 = (const float*)d_in[7];
    const float *b3 = (const float*)d_in[8];
    float *out = (float*)d_out;

    cudaFuncSetAttribute(k_main, cudaFuncAttributeMaxDynamicSharedMemorySize,
                         SM_FLOATS * 4);

    k_prep<<<(NROW * Bq + 255) / 256, 256>>>(v, a);
    k_main<<<NCTA, NTHR, SM_FLOATS * 4>>>(t, W1);
    k_reduce<<<(Bq * N1) / 256, 256>>>(b1);
    k_tail<<<1, 256>>>(W2, b2, W3, b3, out);
}